// round 7
// baseline (speedup 1.0000x reference)
#include <cuda_runtime.h>
#include <cstdint>

// Problem constants (fixed by the dataset)
#define Tn 2000
#define Bn 64
#define Vn 163
#define Ln 200
#define Sn 401          // 2*L+1 extended states
#define NEGF (-1e30f)
#define CHK 14          // states per lane (even => j parity == state parity)
#define NOD 7           // odd (label) states per lane
#define DP  8           // prefetch depth (steps)
#define KMIN (-(1 << 29))

// Packed per-(t,b) row: 4 float2 slots per lane, [slot][lane] layout.
// slot0=(o0,o1) slot1=(o2,o3) slot2=(o4,o5) slot3=(o6, u_blank)
__device__ float2 g_up[Tn * Bn * 128];   // 131 MB
__device__ int    g_eo[Bn * 256];        // per-b gather indices, [b][i*32+lane]
__device__ float  g_lse[Tn * Bn];        // log-sum-exp per (t,b)
__device__ float  g_partial[Bn];         // -(log pe); finalize adds +sum(lse)

// ---------------------------------------------------------------------------
// Kernel 0: per-b static gather-index table (sentinel Vn -> u==0 -> dead state)
// ---------------------------------------------------------------------------
__global__ void eo_kernel(const int* __restrict__ labels,
                          const int* __restrict__ label_lens) {
    int b = blockIdx.x, lane = threadIdx.x;
    int smax = 2 * label_lens[b];
#pragma unroll
    for (int i = 0; i < NOD; i++) {
        int s  = lane * CHK + 2 * i + 1;
        int li = NOD * lane + i;               // (s-1)/2, <= 199 when s <= smax
        int ee = Vn;
        if (s < Sn && s <= smax) ee = labels[b * Ln + li];
        g_eo[(b << 8) + (i << 5) + lane] = ee;
    }
}

// ---------------------------------------------------------------------------
// Kernel 1: one warp per (t,b) row. exp(logits) -> warp smem -> gather via
// eo table -> packed coalesced store. Also lse. No full-u intermediate.
// ---------------------------------------------------------------------------
__global__ __launch_bounds__(256) void prep_kernel(const float* __restrict__ logits) {
    __shared__ float us[8][164];   // per-warp exp row; [163] == 0 sentinel

    int row = blockIdx.x * 8 + (threadIdx.x >> 5);   // row = t*Bn + b
    if (row >= Tn * Bn) return;
    int lane = threadIdx.x & 31;
    int w    = threadIdx.x >> 5;
    int b    = row & (Bn - 1);
    const float* p = logits + (size_t)row * Vn;

    float v[6];
    float m = NEGF;
#pragma unroll
    for (int k = 0; k < 6; k++) {
        int i = lane + 32 * k;
        v[k] = (i < Vn) ? p[i] : NEGF;
        m = fmaxf(m, v[k]);
    }
#pragma unroll
    for (int k = 0; k < 6; k++) {
        int i = lane + 32 * k;
        if (i < 164) us[w][i] = __expf(v[k]);    // i==163 -> exp(NEGF)==0
    }
    __syncwarp();

    // gather this lane's 7 odd-state values from the warp's smem row
    float o[NOD];
#pragma unroll
    for (int i = 0; i < NOD; i++)
        o[i] = us[w][g_eo[(b << 8) + (i << 5) + lane]];
    float ublank = us[w][0];

    float2* dst = g_up + (size_t)row * 128;
    dst[0 * 32 + lane] = make_float2(o[0], o[1]);
    dst[1 * 32 + lane] = make_float2(o[2], o[3]);
    dst[2 * 32 + lane] = make_float2(o[4], o[5]);
    dst[3 * 32 + lane] = make_float2(o[6], ublank);

    // lse reduction
#pragma unroll
    for (int off = 16; off; off >>= 1) m = fmaxf(m, __shfl_xor_sync(0xffffffffu, m, off));
    float sum = 0.f;
#pragma unroll
    for (int k = 0; k < 6; k++) sum += __expf(v[k] - m);
#pragma unroll
    for (int off = 16; off; off >>= 1) sum += __shfl_xor_sync(0xffffffffu, sum, off);
    if (lane == 0) g_lse[row] = m + __logf(sum);
}

// term aligned to kmax: keep (d==0), downshift one 64-bit unit (d==-1), else 0
__device__ __forceinline__ float termf(float m, int d) {
    return (d == 0) ? m : ((d == -1) ? m * 0x1p-64f : 0.f);
}

// ---------------------------------------------------------------------------
// Kernel 2: CTC alpha, one warp per batch element, register-resident.
// Per step: 4 coalesced LDG.64 (pre-packed operands), 1 shuffle, 35 FMA-class.
// Exponent sync/adopt/renorm only at 4-step group boundaries.
// ---------------------------------------------------------------------------
#define PREAMBLE() do {                                                        \
    int nk = __shfl_up_sync(0xffffffffu, kk, 1);                               \
    if (lane == 0) nk = kk;                                                    \
    int d = nk - kk;                                                           \
    float fo = (d <= 0) ? 1.f : ((d == 1) ? 0x1p-64f : 0.f);                   \
    _Pragma("unroll") for (int j = 0; j < CHK; j++) m[j] *= fo;                \
    kk = (d > 0) ? nk : kk;                                                    \
    int dd = (d < 0) ? d : 0;                                                  \
    sc = (dd == 0) ? 1.f : ((dd == -1) ? 0x1p-64f : 0.f);                      \
} while (0)

#define RENORM() do {                                                          \
    float mx = m[0];                                                           \
    _Pragma("unroll") for (int j = 1; j < CHK; j++) mx = fmaxf(mx, m[j]);      \
    float f = 1.f; int dk = 0;                                                 \
    if (mx >= 0x1p32f)                  { f = 0x1p-64f; dk = 1; }              \
    else if (mx < 0x1p-32f && mx > 0.f) { f = 0x1p64f;  dk = -1; }             \
    _Pragma("unroll") for (int j = 0; j < CHK; j++) m[j] *= f;                 \
    kk += dk;                                                                  \
} while (0)

#define BODY(T_, Q_) do {                                                      \
    float nm = __shfl_up_sync(0xffffffffu, m[CHK - 1], 1);                     \
    if (lane == 0) nm = 0.f;                                                   \
    nm *= sc;                                                                  \
    float ob0 = buf[Q_][0].x, ob1 = buf[Q_][0].y;                              \
    float ob2 = buf[Q_][1].x, ob3 = buf[Q_][1].y;                              \
    float ob4 = buf[Q_][2].x, ob5 = buf[Q_][2].y;                              \
    float ob6 = buf[Q_][3].x, ubv = buf[Q_][3].y;                              \
    float nv[CHK];                                                             \
    nv[0]  = (m[0]  + nm) * ubv;                                               \
    nv[1]  = (m[1]  + fmaf(al[0], nm,    m[0]))  * ob0;                        \
    nv[2]  = (m[2]  + m[1])  * ubv;                                            \
    nv[3]  = (m[3]  + fmaf(al[1], m[1],  m[2]))  * ob1;                        \
    nv[4]  = (m[4]  + m[3])  * ubv;                                            \
    nv[5]  = (m[5]  + fmaf(al[2], m[3],  m[4]))  * ob2;                        \
    nv[6]  = (m[6]  + m[5])  * ubv;                                            \
    nv[7]  = (m[7]  + fmaf(al[3], m[5],  m[6]))  * ob3;                        \
    nv[8]  = (m[8]  + m[7])  * ubv;                                            \
    nv[9]  = (m[9]  + fmaf(al[4], m[7],  m[8]))  * ob4;                        \
    nv[10] = (m[10] + m[9])  * ubv;                                            \
    nv[11] = (m[11] + fmaf(al[5], m[9],  m[10])) * ob5;                        \
    nv[12] = (m[12] + m[11]) * ubv;                                            \
    nv[13] = (m[13] + fmaf(al[6], m[11], m[12])) * ob6;                        \
    _Pragma("unroll") for (int j = 0; j < CHK; j++) m[j] = nv[j];              \
    int tp = (T_) + DP; if (tp > Tn - 1) tp = Tn - 1;                          \
    const float2* rp = g_up + (((size_t)tp * Bn + b) << 7) + lane;             \
    buf[Q_][0] = __ldg(rp);                                                    \
    buf[Q_][1] = __ldg(rp + 32);                                               \
    buf[Q_][2] = __ldg(rp + 64);                                               \
    buf[Q_][3] = __ldg(rp + 96);                                               \
} while (0)

__global__ __launch_bounds__(32, 1) void ctc_alpha_kernel(
    const int* __restrict__ labels,
    const int* __restrict__ act_lens,
    const int* __restrict__ label_lens)
{
    const int b    = blockIdx.x;
    const int lane = threadIdx.x;
    const int act  = act_lens[b];
    const int lab  = label_lens[b];
    const int smax = 2 * lab;            // final blank state (lab >= 100)

    // skip-allowed flags for this lane's odd states
    float al[NOD];
#pragma unroll
    for (int i = 0; i < NOD; i++) {
        int s  = lane * CHK + 2 * i + 1;
        int li = NOD * lane + i;
        float af = 0.f;
        if (s >= 3 && s < Sn && s <= smax)
            af = (labels[b * Ln + li] != labels[b * Ln + li - 1]) ? 1.f : 0.f;
        al[i] = af;
    }

    // t = 0 init: state 0 = blank, state 1 = label0 (both on lane 0)
    float m[CHK];
#pragma unroll
    for (int j = 0; j < CHK; j++) m[j] = 0.f;
    {
        const float2* r0 = g_up + ((size_t)b << 7);   // t=0 row
        float2 s0 = __ldg(r0);          // lane-0 slot0: (o0, o1)
        float2 s3 = __ldg(r0 + 96);     // lane-0 slot3: (o6, ublank)
        if (lane == 0) { m[0] = s3.y; m[1] = s0.x; }
    }
    int   kk = 0;
    float sc = 1.f;

    // prologue: slot q holds row 1+q
    float2 buf[DP][4];
#pragma unroll
    for (int q = 0; q < DP; q++) {
        const float2* rp = g_up + (((size_t)(1 + q) * Bn + b) << 7) + lane;
        buf[q][0] = __ldg(rp);
        buf[q][1] = __ldg(rp + 32);
        buf[q][2] = __ldg(rp + 64);
        buf[q][3] = __ldg(rp + 96);
    }

    int t0 = 1;
    for (; t0 + 7 < act; t0 += 8) {      // act >= 1000 always
        PREAMBLE();
        BODY(t0 + 0, 0); BODY(t0 + 1, 1); BODY(t0 + 2, 2); BODY(t0 + 3, 3);
        RENORM();
        PREAMBLE();
        BODY(t0 + 4, 4); BODY(t0 + 5, 5); BODY(t0 + 6, 6); BODY(t0 + 7, 7);
        RENORM();
    }
#pragma unroll
    for (int q = 0; q < 7; q++) {
        if (t0 + q < act) { PREAMBLE(); BODY(t0 + q, q); RENORM(); }
    }

    // publish final alphas and combine
    __shared__ float2 fin[32 * CHK];
#pragma unroll
    for (int j = 0; j < CHK; j++)
        fin[lane * CHK + j] = make_float2(m[j], __int_as_float(kk));
    __syncwarp();

    if (lane == 0) {
        float2 ve = fin[smax], vp2 = fin[smax - 1];
        int ke = (ve.x  > 0.f) ? __float_as_int(ve.y)  : KMIN;
        int kp = (vp2.x > 0.f) ? __float_as_int(vp2.y) : KMIN;
        int km = max(ke, kp);
        float pe = termf(ve.x, ke - km) + termf(vp2.x, kp - km);
        double ll;
        if (km == KMIN || pe <= 0.f) ll = -1e30;   // unreachable in practice
        else ll = log((double)pe) + (double)km * (64.0 * 0.6931471805599453);
        g_partial[b] = (float)(-ll);               // finalize adds +sum(lse)
    }
}

// ---------------------------------------------------------------------------
// Kernel 3: per-b sum of lse over t < act, combine, total = sum/frames.
// ---------------------------------------------------------------------------
__global__ __launch_bounds__(1024, 1) void finalize_kernel(
    const int* __restrict__ act_lens, float* __restrict__ out)
{
    __shared__ float part[16][64];
    __shared__ double red_l[2], red_a[2];

    const int bb = threadIdx.x & 63;
    const int y  = threadIdx.x >> 6;
    const int act = act_lens[bb];

    float sacc = 0.f;
    for (int t = y; t < Tn; t += 16) {
        float v = g_lse[t * Bn + bb];
        sacc += (t < act) ? v : 0.f;
    }
    part[y][bb] = sacc;
    __syncthreads();

    if (threadIdx.x < 64) {
        float tot = 0.f;
#pragma unroll
        for (int k = 0; k < 16; k++) tot += part[k][bb];
        double loss = (double)g_partial[bb] + (double)tot;
        double aln  = (double)act;
#pragma unroll
        for (int o = 16; o; o >>= 1) {
            loss += __shfl_xor_sync(0xffffffffu, loss, o);
            aln  += __shfl_xor_sync(0xffffffffu, aln,  o);
        }
        if ((threadIdx.x & 31) == 0) {
            red_l[threadIdx.x >> 5] = loss;
            red_a[threadIdx.x >> 5] = aln;
        }
    }
    __syncthreads();
    if (threadIdx.x == 0)
        out[0] = (float)((red_l[0] + red_l[1]) / (red_a[0] + red_a[1]));
}

// ---------------------------------------------------------------------------
extern "C" void kernel_launch(void* const* d_in, const int* in_sizes, int n_in,
                              void* d_out, int out_size)
{
    const float* logits     = (const float*)d_in[0];  // [T, B, V]
    const int*   labels     = (const int*)d_in[1];    // [B, L]
    const int*   act_lens   = (const int*)d_in[2];    // [B]
    const int*   label_lens = (const int*)d_in[3];    // [B]

    eo_kernel<<<Bn, 32>>>(labels, label_lens);
    prep_kernel<<<(Tn * Bn + 7) / 8, 256>>>(logits);
    ctc_alpha_kernel<<<Bn, 32>>>(labels, act_lens, label_lens);
    finalize_kernel<<<1, 1024>>>(act_lens, (float*)d_out);
}

// round 8
// speedup vs baseline: 1.3384x; 1.3384x over previous
#include <cuda_runtime.h>
#include <cstdint>

// Problem constants (fixed by the dataset)
#define Tn 2000
#define Bn 64
#define Vn 163
#define Ln 200
#define Sn 401          // 2*L+1 extended states
#define NEGF (-1e30f)
#define CHK 14          // states per lane (even => j parity == state parity)
#define NOD 7           // odd (label) states per lane
#define DP  8           // prefetch depth (steps)
#define KMIN (-(1 << 29))

// Packed per-(t,b) row: 4 float2 slots per lane, [slot][lane] layout.
// slot0=(r0,r1) slot1=(r2,r3) slot2=(r4,r5) slot3=(r6,pad)
// r_i = exp(logit[label_i] - logit[blank])  (blank factor removed from recursion)
__device__ float2 g_up[Tn * Bn * 128];   // 131 MB
__device__ int    g_eo[Bn * 256];        // per-b gather indices, [b][i*32+lane]
__device__ float  g_lse[Tn * Bn];        // adj = lse - logit_blank per (t,b)
__device__ float  g_partial[Bn];         // -(log pe'); finalize adds +sum(adj)

// ---------------------------------------------------------------------------
// Kernel 0: per-b static gather-index table (sentinel 163 -> logit NEGF -> r=0)
// ---------------------------------------------------------------------------
__global__ void eo_kernel(const int* __restrict__ labels,
                          const int* __restrict__ label_lens) {
    int b = blockIdx.x, lane = threadIdx.x;
    int smax = 2 * label_lens[b];
#pragma unroll
    for (int i = 0; i < NOD; i++) {
        int s  = lane * CHK + 2 * i + 1;
        int li = NOD * lane + i;               // (s-1)/2
        int ee = Vn;                           // sentinel
        if (s < Sn && s <= smax) ee = labels[b * Ln + li];
        g_eo[(b << 8) + (i << 5) + lane] = ee;
    }
}

// ---------------------------------------------------------------------------
// Kernel 1: one warp per (t,b) row. Raw logits -> warp smem; computes
// r_i = exp(logit[eo_i] - logit_blank) packed slots, and adj = lse - logit_blank.
// ---------------------------------------------------------------------------
__global__ __launch_bounds__(256) void prep_kernel(const float* __restrict__ logits) {
    __shared__ float us[8][164];   // raw logit row; [163] == NEGF sentinel

    int row = blockIdx.x * 8 + (threadIdx.x >> 5);   // row = t*Bn + b
    if (row >= Tn * Bn) return;
    int lane = threadIdx.x & 31;
    int w    = threadIdx.x >> 5;
    int b    = row & (Bn - 1);
    const float* p = logits + (size_t)row * Vn;

    float v[6];
    float m = NEGF;
#pragma unroll
    for (int k = 0; k < 6; k++) {
        int i = lane + 32 * k;
        v[k] = (i < Vn) ? p[i] : NEGF;
        m = fmaxf(m, v[k]);
        if (i < 164) us[w][i] = v[k];          // i==163 stays NEGF
    }
    __syncwarp();

    float blank = us[w][0];

    // gather and exponentiate this lane's 7 odd-state ratios
    float r[NOD];
#pragma unroll
    for (int i = 0; i < NOD; i++)
        r[i] = __expf(us[w][g_eo[(b << 8) + (i << 5) + lane]] - blank);

    float2* dst = g_up + (size_t)row * 128;
    dst[0 * 32 + lane] = make_float2(r[0], r[1]);
    dst[1 * 32 + lane] = make_float2(r[2], r[3]);
    dst[2 * 32 + lane] = make_float2(r[4], r[5]);
    dst[3 * 32 + lane] = make_float2(r[6], 0.f);

    // lse reduction -> adj = lse - blank
#pragma unroll
    for (int off = 16; off; off >>= 1) m = fmaxf(m, __shfl_xor_sync(0xffffffffu, m, off));
    float sum = 0.f;
#pragma unroll
    for (int k = 0; k < 6; k++) sum += __expf(v[k] - m);
#pragma unroll
    for (int off = 16; off; off >>= 1) sum += __shfl_xor_sync(0xffffffffu, sum, off);
    if (lane == 0) g_lse[row] = m + __logf(sum) - blank;
}

// term aligned to kmax: keep (d==0), downshift one 64-bit unit (d==-1), else 0
__device__ __forceinline__ float termf(float m, int d) {
    return (d == 0) ? m : ((d == -1) ? m * 0x1p-64f : 0.f);
}

// ---------------------------------------------------------------------------
// Kernel 2: CTC alpha (blank-factored), one warp per batch, register-resident.
// Even states: 1 ADD. Odd states: FMA+ADD+MUL by r_i. 4 LDG.64, 1 shuffle/step.
// ---------------------------------------------------------------------------
#define PREAMBLE() do {                                                        \
    int nk = __shfl_up_sync(0xffffffffu, kk, 1);                               \
    if (lane == 0) nk = kk;                                                    \
    int d = nk - kk;                                                           \
    float fo = (d <= 0) ? 1.f : ((d == 1) ? 0x1p-64f : 0.f);                   \
    _Pragma("unroll") for (int j = 0; j < CHK; j++) m[j] *= fo;                \
    kk = (d > 0) ? nk : kk;                                                    \
    int dd = (d < 0) ? d : 0;                                                  \
    sc = (dd == 0) ? 1.f : ((dd == -1) ? 0x1p-64f : 0.f);                      \
} while (0)

#define RENORM() do {                                                          \
    float mx = m[0];                                                           \
    _Pragma("unroll") for (int j = 1; j < CHK; j++) mx = fmaxf(mx, m[j]);      \
    float f = 1.f; int dk = 0;                                                 \
    if (mx >= 0x1p32f)                  { f = 0x1p-64f; dk = 1; }              \
    else if (mx < 0x1p-32f && mx > 0.f) { f = 0x1p64f;  dk = -1; }             \
    _Pragma("unroll") for (int j = 0; j < CHK; j++) m[j] *= f;                 \
    kk += dk;                                                                  \
} while (0)

#define BODY(T_, Q_) do {                                                      \
    float nm = __shfl_up_sync(0xffffffffu, m[CHK - 1], 1);                     \
    if (lane == 0) nm = 0.f;                                                   \
    nm *= sc;                                                                  \
    float r0 = buf[Q_][0].x, r1 = buf[Q_][0].y;                                \
    float r2 = buf[Q_][1].x, r3 = buf[Q_][1].y;                                \
    float r4 = buf[Q_][2].x, r5 = buf[Q_][2].y;                                \
    float r6 = buf[Q_][3].x;                                                   \
    float nv[CHK];                                                             \
    nv[0]  =  m[0]  + nm;                                                      \
    nv[1]  = (m[1]  + fmaf(al[0], nm,    m[0]))  * r0;                         \
    nv[2]  =  m[2]  + m[1];                                                    \
    nv[3]  = (m[3]  + fmaf(al[1], m[1],  m[2]))  * r1;                         \
    nv[4]  =  m[4]  + m[3];                                                    \
    nv[5]  = (m[5]  + fmaf(al[2], m[3],  m[4]))  * r2;                         \
    nv[6]  =  m[6]  + m[5];                                                    \
    nv[7]  = (m[7]  + fmaf(al[3], m[5],  m[6]))  * r3;                         \
    nv[8]  =  m[8]  + m[7];                                                    \
    nv[9]  = (m[9]  + fmaf(al[4], m[7],  m[8]))  * r4;                         \
    nv[10] =  m[10] + m[9];                                                    \
    nv[11] = (m[11] + fmaf(al[5], m[9],  m[10])) * r5;                         \
    nv[12] =  m[12] + m[11];                                                   \
    nv[13] = (m[13] + fmaf(al[6], m[11], m[12])) * r6;                         \
    _Pragma("unroll") for (int j = 0; j < CHK; j++) m[j] = nv[j];              \
    int tp = (T_) + DP; if (tp > Tn - 1) tp = Tn - 1;                          \
    const float2* rp = g_up + (((size_t)tp * Bn + b) << 7) + lane;             \
    buf[Q_][0] = __ldg(rp);                                                    \
    buf[Q_][1] = __ldg(rp + 32);                                               \
    buf[Q_][2] = __ldg(rp + 64);                                               \
    buf[Q_][3] = __ldg(rp + 96);                                               \
} while (0)

__global__ __launch_bounds__(32, 1) void ctc_alpha_kernel(
    const int* __restrict__ labels,
    const int* __restrict__ act_lens,
    const int* __restrict__ label_lens)
{
    const int b    = blockIdx.x;
    const int lane = threadIdx.x;
    const int act  = act_lens[b];
    const int lab  = label_lens[b];
    const int smax = 2 * lab;            // final blank state (lab >= 100)

    // skip-allowed flags for this lane's odd states
    float al[NOD];
#pragma unroll
    for (int i = 0; i < NOD; i++) {
        int s  = lane * CHK + 2 * i + 1;
        int li = NOD * lane + i;
        float af = 0.f;
        if (s >= 3 && s < Sn && s <= smax)
            af = (labels[b * Ln + li] != labels[b * Ln + li - 1]) ? 1.f : 0.f;
        al[i] = af;
    }

    // t = 0 init in blank-factored space: m[0] = 1, m[1] = r0(t=0)
    float m[CHK];
#pragma unroll
    for (int j = 0; j < CHK; j++) m[j] = 0.f;
    {
        const float2* r0p = g_up + ((size_t)b << 7) + lane;
        float2 s0 = __ldg(r0p);          // lane 0 slot0: (r0, r1)
        if (lane == 0) { m[0] = 1.f; m[1] = s0.x; }
    }
    int   kk = 0;
    float sc = 1.f;

    // prologue: slot q holds row 1+q
    float2 buf[DP][4];
#pragma unroll
    for (int q = 0; q < DP; q++) {
        const float2* rp = g_up + (((size_t)(1 + q) * Bn + b) << 7) + lane;
        buf[q][0] = __ldg(rp);
        buf[q][1] = __ldg(rp + 32);
        buf[q][2] = __ldg(rp + 64);
        buf[q][3] = __ldg(rp + 96);
    }

    int t0 = 1;
    for (; t0 + 7 < act; t0 += 8) {      // act >= 1000 always
        PREAMBLE();
        BODY(t0 + 0, 0); BODY(t0 + 1, 1); BODY(t0 + 2, 2); BODY(t0 + 3, 3);
        RENORM();
        PREAMBLE();
        BODY(t0 + 4, 4); BODY(t0 + 5, 5); BODY(t0 + 6, 6); BODY(t0 + 7, 7);
        RENORM();
    }
#pragma unroll
    for (int q = 0; q < 7; q++) {
        if (t0 + q < act) { PREAMBLE(); BODY(t0 + q, q); RENORM(); }
    }

    // publish final alphas and combine
    __shared__ float2 fin[32 * CHK];
#pragma unroll
    for (int j = 0; j < CHK; j++)
        fin[lane * CHK + j] = make_float2(m[j], __int_as_float(kk));
    __syncwarp();

    if (lane == 0) {
        float2 ve = fin[smax], vp2 = fin[smax - 1];
        int ke = (ve.x  > 0.f) ? __float_as_int(ve.y)  : KMIN;
        int kp = (vp2.x > 0.f) ? __float_as_int(vp2.y) : KMIN;
        int km = max(ke, kp);
        float pe = termf(ve.x, ke - km) + termf(vp2.x, kp - km);
        double ll;
        if (km == KMIN || pe <= 0.f) ll = -1e30;   // unreachable in practice
        else ll = log((double)pe) + (double)km * (64.0 * 0.6931471805599453);
        g_partial[b] = (float)(-ll);               // finalize adds +sum(adj)
    }
}

// ---------------------------------------------------------------------------
// Kernel 3: per-b sum of adj over t < act, combine, total = sum/frames.
// ---------------------------------------------------------------------------
__global__ __launch_bounds__(1024, 1) void finalize_kernel(
    const int* __restrict__ act_lens, float* __restrict__ out)
{
    __shared__ float part[16][64];
    __shared__ double red_l[2], red_a[2];

    const int bb = threadIdx.x & 63;
    const int y  = threadIdx.x >> 6;
    const int act = act_lens[bb];

    float sacc = 0.f;
    for (int t = y; t < Tn; t += 16) {
        float v = g_lse[t * Bn + bb];
        sacc += (t < act) ? v : 0.f;
    }
    part[y][bb] = sacc;
    __syncthreads();

    if (threadIdx.x < 64) {
        float tot = 0.f;
#pragma unroll
        for (int k = 0; k < 16; k++) tot += part[k][bb];
        double loss = (double)g_partial[bb] + (double)tot;
        double aln  = (double)act;
#pragma unroll
        for (int o = 16; o; o >>= 1) {
            loss += __shfl_xor_sync(0xffffffffu, loss, o);
            aln  += __shfl_xor_sync(0xffffffffu, aln,  o);
        }
        if ((threadIdx.x & 31) == 0) {
            red_l[threadIdx.x >> 5] = loss;
            red_a[threadIdx.x >> 5] = aln;
        }
    }
    __syncthreads();
    if (threadIdx.x == 0)
        out[0] = (float)((red_l[0] + red_l[1]) / (red_a[0] + red_a[1]));
}

// ---------------------------------------------------------------------------
extern "C" void kernel_launch(void* const* d_in, const int* in_sizes, int n_in,
                              void* d_out, int out_size)
{
    const float* logits     = (const float*)d_in[0];  // [T, B, V]
    const int*   labels     = (const int*)d_in[1];    // [B, L]
    const int*   act_lens   = (const int*)d_in[2];    // [B]
    const int*   label_lens = (const int*)d_in[3];    // [B]

    eo_kernel<<<Bn, 32>>>(labels, label_lens);
    prep_kernel<<<(Tn * Bn + 7) / 8, 256>>>(logits);
    ctc_alpha_kernel<<<Bn, 32>>>(labels, act_lens, label_lens);
    finalize_kernel<<<1, 1024>>>(act_lens, (float*)d_out);
}

// round 9
// speedup vs baseline: 2.2831x; 1.7058x over previous
#include <cuda_runtime.h>
#include <cuda_bf16.h>
#include <cstdint>

// Problem constants (fixed by the dataset)
#define Tn 2000
#define Bn 64
#define Vn 163
#define Ln 200
#define Sn 401          // 2*L+1 extended states
#define NEGF (-1e30f)
#define CHK 14          // states per lane (even => j parity == state parity)
#define NOD 7           // odd (label) states per lane
#define DP  16          // prefetch depth (steps)
#define KMIN (-(1 << 29))

// Packed per-(t,b) row: one uint4 (8 bf16) per lane: (r0,r1)(r2,r3)(r4,r5)(r6,0)
// r_i = exp(logit[label_i] - logit[blank])
__device__ uint4 g_upk[Tn * Bn * 32];    // 65.5 MB
__device__ int   g_eo[Bn * 256];         // per-b gather indices [b][i*32+lane]
__device__ float g_lse[Bn * Tn];         // adj = lse - logit_blank, [b][t] layout
__device__ float g_partial[Bn];          // -(log pe'); sum_kernel adds +sum(adj)
__device__ float g_loss[Bn];             // per-utterance loss

// ---------------------------------------------------------------------------
// Kernel 0: per-b static gather-index table (sentinel 163 -> logit NEGF -> r=0)
// ---------------------------------------------------------------------------
__global__ void eo_kernel(const int* __restrict__ labels,
                          const int* __restrict__ label_lens) {
    int b = blockIdx.x, lane = threadIdx.x;
    int smax = 2 * label_lens[b];
#pragma unroll
    for (int i = 0; i < NOD; i++) {
        int s  = lane * CHK + 2 * i + 1;
        int li = NOD * lane + i;               // (s-1)/2
        int ee = Vn;                           // sentinel
        if (s < Sn && s <= smax) ee = labels[b * Ln + li];
        g_eo[(b << 8) + (i << 5) + lane] = ee;
    }
}

__device__ __forceinline__ uint32_t packbf(float a, float bx) {
    __nv_bfloat162 h = __floats2bfloat162_rn(a, bx);   // x=a(lo), y=bx(hi)
    return *reinterpret_cast<uint32_t*>(&h);
}

// ---------------------------------------------------------------------------
// Kernel 1: one warp per (t,b) row. Raw logits -> warp smem; emits
// bf16-packed r slots and adj = lse - logit_blank (layout [b][t]).
// ---------------------------------------------------------------------------
__global__ __launch_bounds__(256) void prep_kernel(const float* __restrict__ logits) {
    __shared__ float us[8][164];   // raw logit row; [163] == NEGF sentinel

    int row = blockIdx.x * 8 + (threadIdx.x >> 5);   // row = t*Bn + b
    if (row >= Tn * Bn) return;
    int lane = threadIdx.x & 31;
    int w    = threadIdx.x >> 5;
    int b    = row & (Bn - 1);
    int t    = row >> 6;
    const float* p = logits + (size_t)row * Vn;

    float v[6];
    float m = NEGF;
#pragma unroll
    for (int k = 0; k < 6; k++) {
        int i = lane + 32 * k;
        v[k] = (i < Vn) ? p[i] : NEGF;
        m = fmaxf(m, v[k]);
        if (i < 164) us[w][i] = v[k];          // i==163 stays NEGF
    }
    __syncwarp();

    float blank = us[w][0];

    float r[NOD];
#pragma unroll
    for (int i = 0; i < NOD; i++)
        r[i] = __expf(us[w][g_eo[(b << 8) + (i << 5) + lane]] - blank);

    uint4 wd;
    wd.x = packbf(r[0], r[1]);
    wd.y = packbf(r[2], r[3]);
    wd.z = packbf(r[4], r[5]);
    wd.w = packbf(r[6], 0.f);
    g_upk[(size_t)row * 32 + lane] = wd;

    // lse reduction -> adj = lse - blank, stored [b][t]
#pragma unroll
    for (int off = 16; off; off >>= 1) m = fmaxf(m, __shfl_xor_sync(0xffffffffu, m, off));
    float sum = 0.f;
#pragma unroll
    for (int k = 0; k < 6; k++) sum += __expf(v[k] - m);
#pragma unroll
    for (int off = 16; off; off >>= 1) sum += __shfl_xor_sync(0xffffffffu, sum, off);
    if (lane == 0) g_lse[b * Tn + t] = m + __logf(sum) - blank;
}

// term aligned to kmax: keep (d==0), downshift one 64-bit unit (d==-1), else 0
__device__ __forceinline__ float termf(float m, int d) {
    return (d == 0) ? m : ((d == -1) ? m * 0x1p-64f : 0.f);
}

// ---------------------------------------------------------------------------
// Kernel 2: CTC alpha (blank-factored), one warp per batch, register-resident.
// Per step: 1 LDG.128 (8 bf16 ratios), 1 shuffle, 7 unpack ALU, 28 FMA-class.
// Exponent sync/adopt/renorm only at 4-step group boundaries.
// ---------------------------------------------------------------------------
#define PREAMBLE() do {                                                        \
    int nk = __shfl_up_sync(0xffffffffu, kk, 1);                               \
    if (lane == 0) nk = kk;                                                    \
    int d = nk - kk;                                                           \
    float fo = (d <= 0) ? 1.f : ((d == 1) ? 0x1p-64f : 0.f);                   \
    _Pragma("unroll") for (int j = 0; j < CHK; j++) m[j] *= fo;                \
    kk = (d > 0) ? nk : kk;                                                    \
    int dd = (d < 0) ? d : 0;                                                  \
    sc = (dd == 0) ? 1.f : ((dd == -1) ? 0x1p-64f : 0.f);                      \
} while (0)

#define RENORM() do {                                                          \
    float mx = m[0];                                                           \
    _Pragma("unroll") for (int j = 2; j < CHK; j += 2) mx = fmaxf(mx, m[j]);   \
    float f = 1.f; int dk = 0;                                                 \
    if (mx >= 0x1p32f)                  { f = 0x1p-64f; dk = 1; }              \
    else if (mx < 0x1p-32f && mx > 0.f) { f = 0x1p64f;  dk = -1; }             \
    _Pragma("unroll") for (int j = 0; j < CHK; j++) m[j] *= f;                 \
    kk += dk;                                                                  \
} while (0)

#define BODY(T_, Q_) do {                                                      \
    float nm = __shfl_up_sync(0xffffffffu, m[CHK - 1], 1);                     \
    if (lane == 0) nm = 0.f;                                                   \
    nm *= sc;                                                                  \
    uint4 wv = buf[Q_];                                                        \
    float r0 = __uint_as_float(wv.x << 16);                                    \
    float r1 = __uint_as_float(wv.x & 0xFFFF0000u);                            \
    float r2 = __uint_as_float(wv.y << 16);                                    \
    float r3 = __uint_as_float(wv.y & 0xFFFF0000u);                            \
    float r4 = __uint_as_float(wv.z << 16);                                    \
    float r5 = __uint_as_float(wv.z & 0xFFFF0000u);                            \
    float r6 = __uint_as_float(wv.w << 16);                                    \
    float nv[CHK];                                                             \
    nv[0]  =  m[0]  + nm;                                                      \
    nv[1]  = (m[1]  + fmaf(al[0], nm,    m[0]))  * r0;                         \
    nv[2]  =  m[2]  + m[1];                                                    \
    nv[3]  = (m[3]  + fmaf(al[1], m[1],  m[2]))  * r1;                         \
    nv[4]  =  m[4]  + m[3];                                                    \
    nv[5]  = (m[5]  + fmaf(al[2], m[3],  m[4]))  * r2;                         \
    nv[6]  =  m[6]  + m[5];                                                    \
    nv[7]  = (m[7]  + fmaf(al[3], m[5],  m[6]))  * r3;                         \
    nv[8]  =  m[8]  + m[7];                                                    \
    nv[9]  = (m[9]  + fmaf(al[4], m[7],  m[8]))  * r4;                         \
    nv[10] =  m[10] + m[9];                                                    \
    nv[11] = (m[11] + fmaf(al[5], m[9],  m[10])) * r5;                         \
    nv[12] =  m[12] + m[11];                                                   \
    nv[13] = (m[13] + fmaf(al[6], m[11], m[12])) * r6;                         \
    _Pragma("unroll") for (int j = 0; j < CHK; j++) m[j] = nv[j];              \
    int tp = (T_) + DP; if (tp > Tn - 1) tp = Tn - 1;                          \
    buf[Q_] = __ldg(g_upk + ((size_t)tp * Bn + b) * 32 + lane);                \
} while (0)

__global__ __launch_bounds__(32, 1) void ctc_alpha_kernel(
    const int* __restrict__ labels,
    const int* __restrict__ act_lens,
    const int* __restrict__ label_lens)
{
    const int b    = blockIdx.x;
    const int lane = threadIdx.x;
    const int act  = act_lens[b];
    const int lab  = label_lens[b];
    const int smax = 2 * lab;            // final blank state (lab >= 100)

    // skip-allowed flags for this lane's odd states
    float al[NOD];
#pragma unroll
    for (int i = 0; i < NOD; i++) {
        int s  = lane * CHK + 2 * i + 1;
        int li = NOD * lane + i;
        float af = 0.f;
        if (s >= 3 && s < Sn && s <= smax)
            af = (labels[b * Ln + li] != labels[b * Ln + li - 1]) ? 1.f : 0.f;
        al[i] = af;
    }

    // t = 0 init in blank-factored space: m[0] = 1, m[1] = r0(t=0)
    float m[CHK];
#pragma unroll
    for (int j = 0; j < CHK; j++) m[j] = 0.f;
    {
        uint4 w0 = __ldg(g_upk + (size_t)b * 32 + lane);
        if (lane == 0) { m[0] = 1.f; m[1] = __uint_as_float(w0.x << 16); }
    }
    int   kk = 0;
    float sc = 1.f;

    // prologue: slot q holds row 1+q
    uint4 buf[DP];
#pragma unroll
    for (int q = 0; q < DP; q++)
        buf[q] = __ldg(g_upk + ((size_t)(1 + q) * Bn + b) * 32 + lane);

    int t0 = 1;
    for (; t0 + 15 < act; t0 += 16) {    // act >= 1000 always
        PREAMBLE();
        BODY(t0 + 0,  0); BODY(t0 + 1,  1); BODY(t0 + 2,  2); BODY(t0 + 3,  3);
        RENORM();
        PREAMBLE();
        BODY(t0 + 4,  4); BODY(t0 + 5,  5); BODY(t0 + 6,  6); BODY(t0 + 7,  7);
        RENORM();
        PREAMBLE();
        BODY(t0 + 8,  8); BODY(t0 + 9,  9); BODY(t0 + 10, 10); BODY(t0 + 11, 11);
        RENORM();
        PREAMBLE();
        BODY(t0 + 12, 12); BODY(t0 + 13, 13); BODY(t0 + 14, 14); BODY(t0 + 15, 15);
        RENORM();
    }
#pragma unroll
    for (int q = 0; q < 15; q++) {
        if (t0 + q < act) { PREAMBLE(); BODY(t0 + q, q); RENORM(); }
    }

    // publish final alphas and combine
    __shared__ float2 fin[32 * CHK];
#pragma unroll
    for (int j = 0; j < CHK; j++)
        fin[lane * CHK + j] = make_float2(m[j], __int_as_float(kk));
    __syncwarp();

    if (lane == 0) {
        float2 ve = fin[smax], vp2 = fin[smax - 1];
        int ke = (ve.x  > 0.f) ? __float_as_int(ve.y)  : KMIN;
        int kp = (vp2.x > 0.f) ? __float_as_int(vp2.y) : KMIN;
        int km = max(ke, kp);
        float pe = termf(ve.x, ke - km) + termf(vp2.x, kp - km);
        double ll;
        if (km == KMIN || pe <= 0.f) ll = -1e30;   // unreachable in practice
        else ll = log((double)pe) + (double)km * (64.0 * 0.6931471805599453);
        g_partial[b] = (float)(-ll);               // sum_kernel adds +sum(adj)
    }
}

// ---------------------------------------------------------------------------
// Kernel 3a: per-b loss = partial + sum_{t<act} adj.  One block per b.
// ---------------------------------------------------------------------------
__global__ __launch_bounds__(256) void sum_kernel(const int* __restrict__ act_lens)
{
    __shared__ float red[8];
    const int b = blockIdx.x, tid = threadIdx.x;
    const int act = act_lens[b];

    float s = 0.f;
    for (int t = tid; t < act; t += 256) s += g_lse[b * Tn + t];
#pragma unroll
    for (int o = 16; o; o >>= 1) s += __shfl_xor_sync(0xffffffffu, s, o);
    if ((tid & 31) == 0) red[tid >> 5] = s;
    __syncthreads();
    if (tid < 32) {
        float v = (tid < 8) ? red[tid] : 0.f;
#pragma unroll
        for (int o = 4; o; o >>= 1) v += __shfl_xor_sync(0xffffffffu, v, o);
        if (tid == 0) g_loss[b] = g_partial[b] + v;
    }
}

// ---------------------------------------------------------------------------
// Kernel 3b: total = sum(loss) / sum(act_lens). One warp of 64? -> 64 threads.
// ---------------------------------------------------------------------------
__global__ void final_kernel(const int* __restrict__ act_lens,
                             float* __restrict__ out)
{
    int tid = threadIdx.x;  // 64 threads
    double l = (double)g_loss[tid];
    double a = (double)act_lens[tid];
#pragma unroll
    for (int o = 16; o; o >>= 1) {
        l += __shfl_xor_sync(0xffffffffu, l, o);
        a += __shfl_xor_sync(0xffffffffu, a, o);
    }
    __shared__ double sl[2], sa[2];
    if ((tid & 31) == 0) { sl[tid >> 5] = l; sa[tid >> 5] = a; }
    __syncthreads();
    if (tid == 0) out[0] = (float)((sl[0] + sl[1]) / (sa[0] + sa[1]));
}

// ---------------------------------------------------------------------------
extern "C" void kernel_launch(void* const* d_in, const int* in_sizes, int n_in,
                              void* d_out, int out_size)
{
    const float* logits     = (const float*)d_in[0];  // [T, B, V]
    const int*   labels     = (const int*)d_in[1];    // [B, L]
    const int*   act_lens   = (const int*)d_in[2];    // [B]
    const int*   label_lens = (const int*)d_in[3];    // [B]

    eo_kernel<<<Bn, 32>>>(labels, label_lens);
    prep_kernel<<<(Tn * Bn + 7) / 8, 256>>>(logits);
    ctc_alpha_kernel<<<Bn, 32>>>(labels, act_lens, label_lens);
    sum_kernel<<<Bn, 256>>>(act_lens);
    final_kernel<<<1, 64>>>(act_lens, (float*)d_out);
}